// round 9
// baseline (speedup 1.0000x reference)
#include <cuda_runtime.h>
#include <math.h>

#define HW 65536
#define RATIO (127.0f / 255.0f)

// ---------------- scratch (device globals; no allocation) ----------------
__device__ __align__(16) float g_sage[4 * 3 * HW];  // enc planes: mx, av, c1(+b1)
__device__ __align__(16) float g_sagd[4 * 3 * HW];  // dec planes: mx, av, c1(+b1)
__device__ __align__(16) float g_spat[4 * HW];      // sigmoid spatial gate
__device__ float    g_encsum[4 * 128];
__device__ unsigned g_encmax[4 * 128];
__device__ float    g_decmean[4 * 256];
__device__ float    g_decmax [4 * 256];
__device__ __align__(16) float g_ch[4 * 128];       // sigmoid channel gate

// monotone float<->uint map for atomicMax on floats
__device__ __forceinline__ unsigned f2o(float f) {
    unsigned u = __float_as_uint(f);
    return (u & 0x80000000u) ? ~u : (u | 0x80000000u);
}
__device__ __forceinline__ float o2f(unsigned u) {
    return (u & 0x80000000u) ? __uint_as_float(u & 0x7fffffffu) : __uint_as_float(~u);
}

// ================= init (enc atomic targets only) =================
__global__ void k_init() {
    int t = threadIdx.x;
    if (t < 512) { g_encsum[t] = 0.f; g_encmax[t] = 0x007fffffu; }  // f2o(-inf)
}

// ================= fused encoder: planes + channel stats (8 px/thread) =================
// grid (64, 4) x 128 threads: block = 4 rows; thread = (row-pair, float4-col), 2 rows.
__global__ void __launch_bounds__(128) k_enc(const float* __restrict__ xe,
                                             const float* __restrict__ sw1e,
                                             const float* __restrict__ sb1e) {
    __shared__ float sw[128];
    __shared__ float psum[4][128], pmax[4][128];
    const int t = threadIdx.x;
    if (t < 128) sw[t] = sw1e[t];
    __syncthreads();
    const int y0 = blockIdx.x * 4, b = blockIdx.y;
    const int half = t >> 6, c4 = t & 63;
    const int warp = t >> 5, lane = t & 31;
    const int yA = y0 + half * 2;                    // rows yA, yA+1
    const float4* base = (const float4*)(xe + (size_t)b * 128 * HW + yA * 256) + c4;

    float4 mxa = make_float4(-3.4e38f, -3.4e38f, -3.4e38f, -3.4e38f), mxb = mxa;
    float4 sma = make_float4(0.f, 0.f, 0.f, 0.f), smb = sma;
    float4 dta = sma, dtb = sma;
    float racc[4] = {0.f, 0.f, 0.f, 0.f};
    float rmx[4]  = {-3.4e38f, -3.4e38f, -3.4e38f, -3.4e38f};

#pragma unroll
    for (int q = 0; q < 4; q++) {          // channel slot (compile-time)
#pragma unroll 4
        for (int cc = 0; cc < 32; cc++) {  // channel within slot
            const int c = q * 32 + cc;
            float4 va = base[(size_t)c * 16384];
            float4 vb = base[(size_t)c * 16384 + 64];
            float wc = sw[c];
            mxa.x = fmaxf(mxa.x, va.x); sma.x += va.x; dta.x = fmaf(wc, va.x, dta.x);
            mxa.y = fmaxf(mxa.y, va.y); sma.y += va.y; dta.y = fmaf(wc, va.y, dta.y);
            mxa.z = fmaxf(mxa.z, va.z); sma.z += va.z; dta.z = fmaf(wc, va.z, dta.z);
            mxa.w = fmaxf(mxa.w, va.w); sma.w += va.w; dta.w = fmaf(wc, va.w, dta.w);
            mxb.x = fmaxf(mxb.x, vb.x); smb.x += vb.x; dtb.x = fmaf(wc, vb.x, dtb.x);
            mxb.y = fmaxf(mxb.y, vb.y); smb.y += vb.y; dtb.y = fmaf(wc, vb.y, dtb.y);
            mxb.z = fmaxf(mxb.z, vb.z); smb.z += vb.z; dtb.z = fmaf(wc, vb.z, dtb.z);
            mxb.w = fmaxf(mxb.w, vb.w); smb.w += vb.w; dtb.w = fmaf(wc, vb.w, dtb.w);
            float cs = ((va.x + va.y) + (va.z + va.w)) + ((vb.x + vb.y) + (vb.z + vb.w));
            float cm = fmaxf(fmaxf(fmaxf(va.x, va.y), fmaxf(va.z, va.w)),
                             fmaxf(fmaxf(vb.x, vb.y), fmaxf(vb.z, vb.w)));
#pragma unroll
            for (int o = 16; o; o >>= 1) {
                cs += __shfl_xor_sync(0xffffffffu, cs, o);
                cm = fmaxf(cm, __shfl_xor_sync(0xffffffffu, cm, o));
            }
            if (lane == cc) { racc[q] += cs; rmx[q] = fmaxf(rmx[q], cm); }
        }
    }
#pragma unroll
    for (int q = 0; q < 4; q++) {
        psum[warp][q * 32 + lane] = racc[q];
        pmax[warp][q * 32 + lane] = rmx[q];
    }
    __syncthreads();
    if (t < 128) {
        float s = (psum[0][t] + psum[1][t]) + (psum[2][t] + psum[3][t]);
        float m = fmaxf(fmaxf(pmax[0][t], pmax[1][t]), fmaxf(pmax[2][t], pmax[3][t]));
        atomicAdd(&g_encsum[b * 128 + t], s);
        atomicMax(&g_encmax[b * 128 + t], f2o(m));
    }
    const float b1 = sb1e[0];
    sma.x *= (1.f / 128.f); sma.y *= (1.f / 128.f); sma.z *= (1.f / 128.f); sma.w *= (1.f / 128.f);
    smb.x *= (1.f / 128.f); smb.y *= (1.f / 128.f); smb.z *= (1.f / 128.f); smb.w *= (1.f / 128.f);
    dta.x += b1; dta.y += b1; dta.z += b1; dta.w += b1;
    dtb.x += b1; dtb.y += b1; dtb.z += b1; dtb.w += b1;
    const size_t p4 = (size_t)(yA * 256) / 4 + c4;
    float4* eb = (float4*)(g_sage + (size_t)b * 3 * HW);
    eb[p4]                   = mxa;
    eb[p4 + 64]              = mxb;
    eb[HW / 4 + p4]          = sma;
    eb[HW / 4 + p4 + 64]     = smb;
    eb[2 * HW / 4 + p4]      = dta;
    eb[2 * HW / 4 + p4 + 64] = dtb;
}

// ================= decoder per-pixel planes v2: 4 rows/block, h-lerp reuse =================
// grid (64, 4) x 256 threads: block = 4 output rows; thread = column x.
// Stages 4 clamped source rows per channel (always sufficient for 4 outputs);
// 8 channels per double-buffered barrier round.
__global__ void __launch_bounds__(256) k_dec_pix(const float* __restrict__ xd,
                                                 const float* __restrict__ sw1d,
                                                 const float* __restrict__ sb1d) {
    __shared__ float sw[256];
    __shared__ float buf[2][8 * 512];   // [buf][q*512 + srcrow*128 + col]
    const int t = threadIdx.x, b = blockIdx.y;
    const int y0 = blockIdx.x * 4;
    sw[t] = sw1d[t];

    const int rbase = (y0 * 127) / 255;
    int lo[4]; float wy[4];
#pragma unroll
    for (int k = 0; k < 4; k++) {
        const int y = y0 + k;
        const int i0 = (y * 127) / 255;          // exact floor
        lo[k] = i0 - rbase;                      // 0..2, uniform per block
        wy[k] = (float)y * RATIO - (float)i0;
    }
    float px = (float)t * RATIO;
    int j0 = min((int)floorf(px), 127), j1 = min(j0 + 1, 127);
    float wx = px - (float)j0;

    // staging: thread covers source rows (t>>7) and 2+(t>>7), column t&127
    const int gA = min(rbase + (t >> 7), 127) * 128 + (t & 127);
    const int gB = min(rbase + 2 + (t >> 7), 127) * 128 + (t & 127);
    const float* pcb = xd + (size_t)b * 256 * 16384;

#pragma unroll
    for (int q = 0; q < 8; q++) {
        buf[0][q * 512 + t]       = pcb[(size_t)q * 16384 + gA];
        buf[0][q * 512 + 256 + t] = pcb[(size_t)q * 16384 + gB];
    }
    __syncthreads();

    float mx[4] = {0, 0, 0, 0}, sm[4] = {0, 0, 0, 0}, dt[4] = {0, 0, 0, 0};

    for (int g = 0; g < 32; g++) {
        const int cur = g & 1;
        float rr[16];
        const bool pf = (g < 31);
        if (pf) {
            const float* pn = pcb + (size_t)(g + 1) * 8 * 16384;
#pragma unroll
            for (int q = 0; q < 8; q++) {
                rr[q * 2]     = pn[(size_t)q * 16384 + gA];
                rr[q * 2 + 1] = pn[(size_t)q * 16384 + gB];
            }
        }
#pragma unroll
        for (int q = 0; q < 8; q++) {
            const int c = g * 8 + q;
            const float* S = &buf[cur][q * 512];
            float h0, h1, h2, h3;
            { float a = S[j0],       bb = S[j1];       h0 = fmaf(wx, bb - a, a); }
            { float a = S[128 + j0], bb = S[128 + j1]; h1 = fmaf(wx, bb - a, a); }
            { float a = S[256 + j0], bb = S[256 + j1]; h2 = fmaf(wx, bb - a, a); }
            { float a = S[384 + j0], bb = S[384 + j1]; h3 = fmaf(wx, bb - a, a); }
            const float wc = sw[c];
#pragma unroll
            for (int k = 0; k < 4; k++) {
                float hl = (lo[k] == 0) ? h0 : ((lo[k] == 1) ? h1 : h2);
                float hh = (lo[k] == 0) ? h1 : ((lo[k] == 1) ? h2 : h3);
                float v = fmaf(wy[k], hh - hl, hl);
                v = fmaxf(v, 0.f);
                mx[k] = fmaxf(mx[k], v);
                sm[k] += v;
                dt[k] = fmaf(wc, v, dt[k]);
            }
        }
        if (pf) {
#pragma unroll
            for (int q = 0; q < 8; q++) {
                buf[cur ^ 1][q * 512 + t]       = rr[q * 2];
                buf[cur ^ 1][q * 512 + 256 + t] = rr[q * 2 + 1];
            }
        }
        __syncthreads();
    }
    const float b1 = sb1d[0];
    const size_t db = (size_t)b * 3 * HW;
#pragma unroll
    for (int k = 0; k < 4; k++) {
        const int p = (y0 + k) * 256 + t;
        g_sagd[db + p]          = mx[k];
        g_sagd[db + HW + p]     = sm[k] * (1.f / 256.f);
        g_sagd[db + 2 * HW + p] = dt[k] + b1;
    }
}

// ================= decoder channel stats (whole-channel smem + h-reuse) =================
// grid (256, 4): c = blockIdx.x, b = blockIdx.y, 256 threads (thread = output column).
__global__ void __launch_bounds__(256) k_dec_red(const float* __restrict__ xd) {
    __shared__ float S[65 * 128];
    __shared__ float rsum[256], rmax[256];
    const int c = blockIdx.x, b = blockIdx.y, t = threadIdx.x;
    const float* pc = xd + ((size_t)b * 256 + c) * 16384;

    float px = (float)t * RATIO;
    int j0 = min((int)floorf(px), 127), j1 = min(j0 + 1, 127);
    float wx = px - (float)j0;

    float s = 0.f, m = 0.f;

#pragma unroll
    for (int ph = 0; ph < 2; ph++) {
        const int poff = ph ? 63 : 0;
        if (ph) __syncthreads();
        {
            const float4* gsrc = (const float4*)(pc + poff * 128);
            float4* sdst = (float4*)S;
            for (int i = t; i < 65 * 32; i += 256) sdst[i] = gsrc[i];
        }
        __syncthreads();
#pragma unroll
        for (int k = 0; k < 4; k++) {
            const int y0 = ph * 128 + k * 32;
            const int rbase = (y0 * 127) / 255;
            float h[18];
#pragma unroll
            for (int r = 0; r < 18; r++) {
                const int row = min(rbase + r, 127) - poff;
                const float a = S[row * 128 + j0];
                h[r] = fmaf(wx, S[row * 128 + j1] - a, a);
            }
#pragma unroll
            for (int j = 0; j < 32; j++) {
                const int y  = y0 + j;
                const int i0 = (y * 127) / 255;
                const int i1 = min(i0 + 1, 127);
                const float wy = (float)y * RATIO - (float)i0;
                const float vlo = h[i0 - rbase], vhi = h[i1 - rbase];
                float v = fmaf(wy, vhi - vlo, vlo);
                v = fmaxf(v, 0.f);
                s += v;
                m = fmaxf(m, v);
            }
        }
    }
    __syncthreads();
    rsum[t] = s; rmax[t] = m;
    __syncthreads();
    for (int o = 128; o > 0; o >>= 1) {
        if (t < o) {
            rsum[t] += rsum[t + o];
            rmax[t] = fmaxf(rmax[t], rmax[t + o]);
        }
        __syncthreads();
    }
    if (t == 0) {
        g_decmean[b * 256 + c] = rsum[0] * (1.f / 65536.f);
        g_decmax [b * 256 + c] = rmax[0];
    }
}

// ================= channel MLP (parallel) =================
__global__ void __launch_bounds__(256) k_mlp(
        const float* __restrict__ cwea, const float* __restrict__ cbea,
        const float* __restrict__ cwem, const float* __restrict__ cbem,
        const float* __restrict__ cwda, const float* __restrict__ cbda,
        const float* __restrict__ cwdm, const float* __restrict__ cbdm,
        const float* __restrict__ cwf,  const float* __restrict__ cbf) {
    __shared__ float part[256];
    __shared__ float tsm[16];
    const int b = blockIdx.x, t = threadIdx.x;
    const int n = t >> 4, ck = t & 15;
    float acc = 0.f;
#pragma unroll
    for (int i = 0; i < 8; i++) {
        int c = ck * 8 + i;
        acc += g_encsum[b * 128 + c] * (1.f / 65536.f) * cwea[n * 128 + c]
             + o2f(g_encmax[b * 128 + c]) * cwem[n * 128 + c];
    }
#pragma unroll
    for (int i = 0; i < 16; i++) {
        int c = ck * 16 + i;
        acc += g_decmean[b * 256 + c] * cwda[n * 256 + c]
             + g_decmax [b * 256 + c] * cwdm[n * 256 + c];
    }
    if (ck == 0) acc += cbea[n] + cbem[n] + cbda[n] + cbdm[n];
    part[t] = acc;
    __syncthreads();
    for (int o = 8; o > 0; o >>= 1) {
        if (ck < o) part[t] += part[t + o];
        __syncthreads();
    }
    if (ck == 0) tsm[n] = part[t];
    __syncthreads();
    if (t < 128) {
        float a = cbf[t];
#pragma unroll
        for (int q = 0; q < 16; q++) a = fmaf(tsm[q], cwf[t * 16 + q], a);
        g_ch[b * 128 + t] = 1.f / (1.f + __expf(-a));
    }
}

// ================= fused 7x7 conv (6 planes) + sigmoid =================
__global__ void __launch_bounds__(256) k_conv(const float* __restrict__ sw2e,
                                              const float* __restrict__ sw2d,
                                              const float* __restrict__ sb2e,
                                              const float* __restrict__ sb2d) {
    __shared__ float pl[6][22 * 22];
    __shared__ float wsm[294];
    __shared__ float bv;
    const int tid = threadIdx.x;
    const int X0 = blockIdx.x * 16, Y0 = blockIdx.y * 16, b = blockIdx.z;
    for (int i = tid; i < 294; i += 256)
        wsm[i] = (i < 147) ? sw2e[i] : sw2d[i - 147];
    if (tid == 0) bv = sb2e[0] + sb2d[0];
    const size_t eb = (size_t)b * 3 * HW;
    for (int idx = tid; idx < 22 * 22; idx += 256) {
        int ry = idx / 22, rx = idx - ry * 22;
        int gy = Y0 + ry - 3, gx = X0 + rx - 3;
        float v0 = 0, v1 = 0, v2 = 0, v3 = 0, v4 = 0, v5 = 0;
        if (gy >= 0 && gy < 256 && gx >= 0 && gx < 256) {
            int p = gy * 256 + gx;
            v0 = g_sage[eb + p];
            v1 = g_sage[eb + HW + p];
            v2 = g_sage[eb + 2 * HW + p];
            v3 = g_sagd[eb + p];
            v4 = g_sagd[eb + HW + p];
            v5 = g_sagd[eb + 2 * HW + p];
        }
        pl[0][idx] = v0; pl[1][idx] = v1; pl[2][idx] = v2;
        pl[3][idx] = v3; pl[4][idx] = v4; pl[5][idx] = v5;
    }
    __syncthreads();
    const int tx = tid & 15, ty = tid >> 4;
    float acc = bv;
    for (int pp = 0; pp < 6; pp++)
#pragma unroll
        for (int ky = 0; ky < 7; ky++)
#pragma unroll
            for (int kx = 0; kx < 7; kx++)
                acc = fmaf(pl[pp][(ty + ky) * 22 + tx + kx], wsm[pp * 49 + ky * 7 + kx], acc);
    g_spat[(size_t)b * HW + (Y0 + ty) * 256 + X0 + tx] = 1.f / (1.f + __expf(-acc));
}

// ================= final multiply =================
__global__ void __launch_bounds__(256) k_final(const float* __restrict__ xe,
                                               float* __restrict__ out) {
    const int bc = blockIdx.y;
    const int b  = bc >> 7;
    const int i  = blockIdx.x * 256 + threadIdx.x;
    const float s = g_ch[bc];
    float4 xv = reinterpret_cast<const float4*>(xe)[(size_t)bc * 16384 + i];
    float4 sp = reinterpret_cast<const float4*>(g_spat)[(size_t)b * 16384 + i];
    float4 o;
    o.x = xv.x * sp.x * s;
    o.y = xv.y * sp.y * s;
    o.z = xv.z * sp.z * s;
    o.w = xv.w * sp.w * s;
    reinterpret_cast<float4*>(out)[(size_t)bc * 16384 + i] = o;
}

// ================= launch =================
extern "C" void kernel_launch(void* const* d_in, const int* in_sizes, int n_in,
                              void* d_out, int out_size) {
    const float* xe   = (const float*)d_in[0];
    const float* xd   = (const float*)d_in[1];
    const float* cwea = (const float*)d_in[2];
    const float* cbea = (const float*)d_in[3];
    const float* cwem = (const float*)d_in[4];
    const float* cbem = (const float*)d_in[5];
    const float* cwda = (const float*)d_in[6];
    const float* cbda = (const float*)d_in[7];
    const float* cwdm = (const float*)d_in[8];
    const float* cbdm = (const float*)d_in[9];
    const float* cwf  = (const float*)d_in[10];
    const float* cbf  = (const float*)d_in[11];
    const float* sw1e = (const float*)d_in[12];
    const float* sb1e = (const float*)d_in[13];
    const float* sw2e = (const float*)d_in[14];
    const float* sb2e = (const float*)d_in[15];
    const float* sw1d = (const float*)d_in[16];
    const float* sb1d = (const float*)d_in[17];
    const float* sw2d = (const float*)d_in[18];
    const float* sb2d = (const float*)d_in[19];
    float* out = (float*)d_out;

    k_init<<<1, 512>>>();
    k_enc<<<dim3(64, 4), 128>>>(xe, sw1e, sb1e);
    k_dec_pix<<<dim3(64, 4), 256>>>(xd, sw1d, sb1d);
    k_dec_red<<<dim3(256, 4), 256>>>(xd);
    k_mlp<<<4, 256>>>(cwea, cbea, cwem, cbem, cwda, cbda, cwdm, cbdm, cwf, cbf);
    k_conv<<<dim3(16, 16, 4), 256>>>(sw2e, sw2d, sb2e, sb2d);
    k_final<<<dim3(64, 512), 256>>>(xe, out);
}

// round 10
// speedup vs baseline: 1.1880x; 1.1880x over previous
#include <cuda_runtime.h>
#include <math.h>

#define HW 65536
#define RATIO (127.0f / 255.0f)

// ---------------- scratch (device globals; no allocation) ----------------
__device__ __align__(16) float g_sage[4 * 3 * HW];  // enc planes: mx, av, c1(+b1)
__device__ __align__(16) float g_sagd[8 * 3 * HW];  // dec PARTIAL planes per (half,b): mx, sum, dot
__device__ __align__(16) float g_spat[4 * HW];      // sigmoid spatial gate
__device__ float    g_encsum[4 * 128];
__device__ unsigned g_encmax[4 * 128];
__device__ float    g_decmean[4 * 256];
__device__ float    g_decmax [4 * 256];
__device__ __align__(16) float g_ch[4 * 128];       // sigmoid channel gate

// monotone float<->uint map for atomicMax on floats
__device__ __forceinline__ unsigned f2o(float f) {
    unsigned u = __float_as_uint(f);
    return (u & 0x80000000u) ? ~u : (u | 0x80000000u);
}
__device__ __forceinline__ float o2f(unsigned u) {
    return (u & 0x80000000u) ? __uint_as_float(u & 0x7fffffffu) : __uint_as_float(~u);
}

// ================= init (enc atomic targets only) =================
__global__ void k_init() {
    int t = threadIdx.x;
    if (t < 512) { g_encsum[t] = 0.f; g_encmax[t] = 0x007fffffu; }  // f2o(-inf)
}

// ================= fused encoder: planes + channel stats (R8 version) =================
// grid (128, 4) x 128 threads: block = 2 rows; thread = (row, float4-col)
__global__ void __launch_bounds__(128) k_enc(const float* __restrict__ xe,
                                             const float* __restrict__ sw1e,
                                             const float* __restrict__ sb1e) {
    __shared__ float sw[128];
    __shared__ float psum[4][128], pmax[4][128];
    const int t = threadIdx.x;
    if (t < 128) sw[t] = sw1e[t];
    __syncthreads();
    const int y = blockIdx.x * 2 + (t >> 6), c4 = t & 63, b = blockIdx.y;
    const int warp = t >> 5, lane = t & 31;
    const float4* base = (const float4*)(xe + (size_t)b * 128 * HW + y * 256) + c4;

    float4 mx = make_float4(-3.4e38f, -3.4e38f, -3.4e38f, -3.4e38f);
    float4 sm = make_float4(0.f, 0.f, 0.f, 0.f);
    float4 dt = make_float4(0.f, 0.f, 0.f, 0.f);
    float racc[4] = {0.f, 0.f, 0.f, 0.f};
    float rmx[4]  = {-3.4e38f, -3.4e38f, -3.4e38f, -3.4e38f};

#pragma unroll
    for (int q = 0; q < 4; q++) {
#pragma unroll 4
        for (int cc = 0; cc < 32; cc++) {
            const int c = q * 32 + cc;
            float4 v = base[(size_t)c * (HW / 4)];
            float wc = sw[c];
            mx.x = fmaxf(mx.x, v.x); sm.x += v.x; dt.x = fmaf(wc, v.x, dt.x);
            mx.y = fmaxf(mx.y, v.y); sm.y += v.y; dt.y = fmaf(wc, v.y, dt.y);
            mx.z = fmaxf(mx.z, v.z); sm.z += v.z; dt.z = fmaf(wc, v.z, dt.z);
            mx.w = fmaxf(mx.w, v.w); sm.w += v.w; dt.w = fmaf(wc, v.w, dt.w);
            float cs = (v.x + v.y) + (v.z + v.w);
            float cm = fmaxf(fmaxf(v.x, v.y), fmaxf(v.z, v.w));
#pragma unroll
            for (int o = 16; o; o >>= 1) {
                cs += __shfl_xor_sync(0xffffffffu, cs, o);
                cm = fmaxf(cm, __shfl_xor_sync(0xffffffffu, cm, o));
            }
            if (lane == cc) { racc[q] += cs; rmx[q] = fmaxf(rmx[q], cm); }
        }
    }
#pragma unroll
    for (int q = 0; q < 4; q++) {
        psum[warp][q * 32 + lane] = racc[q];
        pmax[warp][q * 32 + lane] = rmx[q];
    }
    __syncthreads();
    if (t < 128) {
        float s = (psum[0][t] + psum[1][t]) + (psum[2][t] + psum[3][t]);
        float m = fmaxf(fmaxf(pmax[0][t], pmax[1][t]), fmaxf(pmax[2][t], pmax[3][t]));
        atomicAdd(&g_encsum[b * 128 + t], s);
        atomicMax(&g_encmax[b * 128 + t], f2o(m));
    }
    const float b1 = sb1e[0];
    sm.x *= (1.f / 128.f); sm.y *= (1.f / 128.f); sm.z *= (1.f / 128.f); sm.w *= (1.f / 128.f);
    dt.x += b1; dt.y += b1; dt.z += b1; dt.w += b1;
    const size_t p4 = (size_t)(y * 256) / 4 + c4;
    float4* eb = (float4*)(g_sage + (size_t)b * 3 * HW);
    eb[p4]              = mx;
    eb[HW / 4 + p4]     = sm;
    eb[2 * HW / 4 + p4] = dt;
}

// ================= decoder per-pixel partial planes: 4 rows/block, channel-half split =================
// grid (64, 2, 4): x = row-group (4 rows), y = channel half, z = b. 256 threads = columns.
// Writes PARTIAL (mx, raw sum, raw dot) per (half,b); k_conv combines.
__global__ void __launch_bounds__(256) k_dec_pix(const float* __restrict__ xd,
                                                 const float* __restrict__ sw1d) {
    __shared__ float sw[128];
    __shared__ float buf[2][8 * 512];   // [buf][q*512 + srcrow*128 + col]
    const int t = threadIdx.x, half = blockIdx.y, b = blockIdx.z;
    const int y0 = blockIdx.x * 4;
    if (t < 128) sw[t] = sw1d[half * 128 + t];

    const int rbase = (y0 * 127) / 255;
    int lo[4]; float wy[4];
#pragma unroll
    for (int k = 0; k < 4; k++) {
        const int y = y0 + k;
        const int i0 = (y * 127) / 255;          // exact floor
        lo[k] = i0 - rbase;                      // 0..2, uniform per block
        wy[k] = (float)y * RATIO - (float)i0;
    }
    float px = (float)t * RATIO;
    int j0 = min((int)floorf(px), 127), j1 = min(j0 + 1, 127);
    float wx = px - (float)j0;

    const int gA = min(rbase + (t >> 7), 127) * 128 + (t & 127);
    const int gB = min(rbase + 2 + (t >> 7), 127) * 128 + (t & 127);
    const float* pcb = xd + ((size_t)b * 256 + half * 128) * 16384;

#pragma unroll
    for (int q = 0; q < 8; q++) {
        buf[0][q * 512 + t]       = pcb[(size_t)q * 16384 + gA];
        buf[0][q * 512 + 256 + t] = pcb[(size_t)q * 16384 + gB];
    }
    __syncthreads();

    float mx[4] = {0, 0, 0, 0}, sm[4] = {0, 0, 0, 0}, dt[4] = {0, 0, 0, 0};

    for (int g = 0; g < 16; g++) {
        const int cur = g & 1;
        float rr[16];
        const bool pf = (g < 15);
        if (pf) {
            const float* pn = pcb + (size_t)(g + 1) * 8 * 16384;
#pragma unroll
            for (int q = 0; q < 8; q++) {
                rr[q * 2]     = pn[(size_t)q * 16384 + gA];
                rr[q * 2 + 1] = pn[(size_t)q * 16384 + gB];
            }
        }
#pragma unroll
        for (int q = 0; q < 8; q++) {
            const int c = g * 8 + q;
            const float* S = &buf[cur][q * 512];
            float h0, h1, h2, h3;
            { float a = S[j0],       bb = S[j1];       h0 = fmaf(wx, bb - a, a); }
            { float a = S[128 + j0], bb = S[128 + j1]; h1 = fmaf(wx, bb - a, a); }
            { float a = S[256 + j0], bb = S[256 + j1]; h2 = fmaf(wx, bb - a, a); }
            { float a = S[384 + j0], bb = S[384 + j1]; h3 = fmaf(wx, bb - a, a); }
            const float wc = sw[c];
#pragma unroll
            for (int k = 0; k < 4; k++) {
                float hl = (lo[k] == 0) ? h0 : ((lo[k] == 1) ? h1 : h2);
                float hh = (lo[k] == 0) ? h1 : ((lo[k] == 1) ? h2 : h3);
                float v = fmaf(wy[k], hh - hl, hl);
                v = fmaxf(v, 0.f);
                mx[k] = fmaxf(mx[k], v);
                sm[k] += v;
                dt[k] = fmaf(wc, v, dt[k]);
            }
        }
        if (pf) {
#pragma unroll
            for (int q = 0; q < 8; q++) {
                buf[cur ^ 1][q * 512 + t]       = rr[q * 2];
                buf[cur ^ 1][q * 512 + 256 + t] = rr[q * 2 + 1];
            }
        }
        __syncthreads();
    }
    const size_t db = (size_t)(half * 4 + b) * 3 * HW;
#pragma unroll
    for (int k = 0; k < 4; k++) {
        const int p = (y0 + k) * 256 + t;
        g_sagd[db + p]          = mx[k];
        g_sagd[db + HW + p]     = sm[k];
        g_sagd[db + 2 * HW + p] = dt[k];
    }
}

// ================= decoder channel stats (whole-channel smem + h-reuse) =================
// grid (256, 4): c = blockIdx.x, b = blockIdx.y, 256 threads (thread = output column).
__global__ void __launch_bounds__(256) k_dec_red(const float* __restrict__ xd) {
    __shared__ float S[65 * 128];
    __shared__ float rsum[256], rmax[256];
    const int c = blockIdx.x, b = blockIdx.y, t = threadIdx.x;
    const float* pc = xd + ((size_t)b * 256 + c) * 16384;

    float px = (float)t * RATIO;
    int j0 = min((int)floorf(px), 127), j1 = min(j0 + 1, 127);
    float wx = px - (float)j0;

    float s = 0.f, m = 0.f;

#pragma unroll
    for (int ph = 0; ph < 2; ph++) {
        const int poff = ph ? 63 : 0;
        if (ph) __syncthreads();
        {
            const float4* gsrc = (const float4*)(pc + poff * 128);
            float4* sdst = (float4*)S;
            for (int i = t; i < 65 * 32; i += 256) sdst[i] = gsrc[i];
        }
        __syncthreads();
#pragma unroll
        for (int k = 0; k < 4; k++) {
            const int y0 = ph * 128 + k * 32;
            const int rbase = (y0 * 127) / 255;
            float h[18];
#pragma unroll
            for (int r = 0; r < 18; r++) {
                const int row = min(rbase + r, 127) - poff;
                const float a = S[row * 128 + j0];
                h[r] = fmaf(wx, S[row * 128 + j1] - a, a);
            }
#pragma unroll
            for (int j = 0; j < 32; j++) {
                const int y  = y0 + j;
                const int i0 = (y * 127) / 255;
                const int i1 = min(i0 + 1, 127);
                const float wy = (float)y * RATIO - (float)i0;
                const float vlo = h[i0 - rbase], vhi = h[i1 - rbase];
                float v = fmaf(wy, vhi - vlo, vlo);
                v = fmaxf(v, 0.f);
                s += v;
                m = fmaxf(m, v);
            }
        }
    }
    __syncthreads();
    rsum[t] = s; rmax[t] = m;
    __syncthreads();
    for (int o = 128; o > 0; o >>= 1) {
        if (t < o) {
            rsum[t] += rsum[t + o];
            rmax[t] = fmaxf(rmax[t], rmax[t + o]);
        }
        __syncthreads();
    }
    if (t == 0) {
        g_decmean[b * 256 + c] = rsum[0] * (1.f / 65536.f);
        g_decmax [b * 256 + c] = rmax[0];
    }
}

// ================= channel MLP (parallel) =================
__global__ void __launch_bounds__(256) k_mlp(
        const float* __restrict__ cwea, const float* __restrict__ cbea,
        const float* __restrict__ cwem, const float* __restrict__ cbem,
        const float* __restrict__ cwda, const float* __restrict__ cbda,
        const float* __restrict__ cwdm, const float* __restrict__ cbdm,
        const float* __restrict__ cwf,  const float* __restrict__ cbf) {
    __shared__ float part[256];
    __shared__ float tsm[16];
    const int b = blockIdx.x, t = threadIdx.x;
    const int n = t >> 4, ck = t & 15;
    float acc = 0.f;
#pragma unroll
    for (int i = 0; i < 8; i++) {
        int c = ck * 8 + i;
        acc += g_encsum[b * 128 + c] * (1.f / 65536.f) * cwea[n * 128 + c]
             + o2f(g_encmax[b * 128 + c]) * cwem[n * 128 + c];
    }
#pragma unroll
    for (int i = 0; i < 16; i++) {
        int c = ck * 16 + i;
        acc += g_decmean[b * 256 + c] * cwda[n * 256 + c]
             + g_decmax [b * 256 + c] * cwdm[n * 256 + c];
    }
    if (ck == 0) acc += cbea[n] + cbem[n] + cbda[n] + cbdm[n];
    part[t] = acc;
    __syncthreads();
    for (int o = 8; o > 0; o >>= 1) {
        if (ck < o) part[t] += part[t + o];
        __syncthreads();
    }
    if (ck == 0) tsm[n] = part[t];
    __syncthreads();
    if (t < 128) {
        float a = cbf[t];
#pragma unroll
        for (int q = 0; q < 16; q++) a = fmaf(tsm[q], cwf[t * 16 + q], a);
        g_ch[b * 128 + t] = 1.f / (1.f + __expf(-a));
    }
}

// ================= fused 7x7 conv (6 planes, combines dec halves) + sigmoid =================
// grid (16, 16, 4): 16x16 output tile, 256 threads, 1 output/thread
__global__ void __launch_bounds__(256) k_conv(const float* __restrict__ sw2e,
                                              const float* __restrict__ sw2d,
                                              const float* __restrict__ sb2e,
                                              const float* __restrict__ sb2d,
                                              const float* __restrict__ sb1d) {
    __shared__ float pl[6][22 * 22];
    __shared__ float wsm[294];
    __shared__ float bv;
    const int tid = threadIdx.x;
    const int X0 = blockIdx.x * 16, Y0 = blockIdx.y * 16, b = blockIdx.z;
    for (int i = tid; i < 294; i += 256)
        wsm[i] = (i < 147) ? sw2e[i] : sw2d[i - 147];
    if (tid == 0) bv = sb2e[0] + sb2d[0];
    const float sb1 = __ldg(sb1d);
    const size_t eb = (size_t)b * 3 * HW;
    const size_t d0 = (size_t)b * 3 * HW;        // half 0
    const size_t d1 = (size_t)(4 + b) * 3 * HW;  // half 1
    for (int idx = tid; idx < 22 * 22; idx += 256) {
        int ry = idx / 22, rx = idx - ry * 22;
        int gy = Y0 + ry - 3, gx = X0 + rx - 3;
        float v0 = 0, v1 = 0, v2 = 0, v3 = 0, v4 = 0, v5 = 0;
        if (gy >= 0 && gy < 256 && gx >= 0 && gx < 256) {
            int p = gy * 256 + gx;
            v0 = g_sage[eb + p];
            v1 = g_sage[eb + HW + p];
            v2 = g_sage[eb + 2 * HW + p];
            v3 = fmaxf(g_sagd[d0 + p], g_sagd[d1 + p]);
            v4 = (g_sagd[d0 + HW + p] + g_sagd[d1 + HW + p]) * (1.f / 256.f);
            v5 = g_sagd[d0 + 2 * HW + p] + g_sagd[d1 + 2 * HW + p] + sb1;
        }
        pl[0][idx] = v0; pl[1][idx] = v1; pl[2][idx] = v2;
        pl[3][idx] = v3; pl[4][idx] = v4; pl[5][idx] = v5;
    }
    __syncthreads();
    const int tx = tid & 15, ty = tid >> 4;
    float acc = bv;
    for (int pp = 0; pp < 6; pp++)
#pragma unroll
        for (int ky = 0; ky < 7; ky++)
#pragma unroll
            for (int kx = 0; kx < 7; kx++)
                acc = fmaf(pl[pp][(ty + ky) * 22 + tx + kx], wsm[pp * 49 + ky * 7 + kx], acc);
    g_spat[(size_t)b * HW + (Y0 + ty) * 256 + X0 + tx] = 1.f / (1.f + __expf(-acc));
}

// ================= final multiply =================
__global__ void __launch_bounds__(256) k_final(const float* __restrict__ xe,
                                               float* __restrict__ out) {
    const int bc = blockIdx.y;
    const int b  = bc >> 7;
    const int i  = blockIdx.x * 256 + threadIdx.x;
    const float s = g_ch[bc];
    float4 xv = reinterpret_cast<const float4*>(xe)[(size_t)bc * 16384 + i];
    float4 sp = reinterpret_cast<const float4*>(g_spat)[(size_t)b * 16384 + i];
    float4 o;
    o.x = xv.x * sp.x * s;
    o.y = xv.y * sp.y * s;
    o.z = xv.z * sp.z * s;
    o.w = xv.w * sp.w * s;
    reinterpret_cast<float4*>(out)[(size_t)bc * 16384 + i] = o;
}

// ================= launch =================
extern "C" void kernel_launch(void* const* d_in, const int* in_sizes, int n_in,
                              void* d_out, int out_size) {
    const float* xe   = (const float*)d_in[0];
    const float* xd   = (const float*)d_in[1];
    const float* cwea = (const float*)d_in[2];
    const float* cbea = (const float*)d_in[3];
    const float* cwem = (const float*)d_in[4];
    const float* cbem = (const float*)d_in[5];
    const float* cwda = (const float*)d_in[6];
    const float* cbda = (const float*)d_in[7];
    const float* cwdm = (const float*)d_in[8];
    const float* cbdm = (const float*)d_in[9];
    const float* cwf  = (const float*)d_in[10];
    const float* cbf  = (const float*)d_in[11];
    const float* sw1e = (const float*)d_in[12];
    const float* sb1e = (const float*)d_in[13];
    const float* sw2e = (const float*)d_in[14];
    const float* sb2e = (const float*)d_in[15];
    const float* sw1d = (const float*)d_in[16];
    const float* sb1d = (const float*)d_in[17];
    const float* sw2d = (const float*)d_in[18];
    const float* sb2d = (const float*)d_in[19];
    float* out = (float*)d_out;

    k_init<<<1, 512>>>();
    k_enc<<<dim3(128, 4), 128>>>(xe, sw1e, sb1e);
    k_dec_pix<<<dim3(64, 2, 4), 256>>>(xd, sw1d);
    k_dec_red<<<dim3(256, 4), 256>>>(xd);
    k_mlp<<<4, 256>>>(cwea, cbea, cwem, cbem, cwda, cbda, cwdm, cbdm, cwf, cbf);
    k_conv<<<dim3(16, 16, 4), 256>>>(sw2e, sw2d, sb2e, sb2d, sb1d);
    k_final<<<dim3(64, 512), 256>>>(xe, out);
}

// round 11
// speedup vs baseline: 1.2051x; 1.0144x over previous
#include <cuda_runtime.h>
#include <math.h>

#define HW 65536
#define RATIO (127.0f / 255.0f)

// ---------------- scratch (device globals; no allocation) ----------------
__device__ __align__(16) float g_sage[4 * 3 * HW];  // enc planes: mx, av, c1(+b1)
__device__ __align__(16) float g_sagd[8 * 3 * HW];  // dec PARTIAL planes per (half,b): mx, sum, dot
__device__ __align__(16) float g_spat[4 * HW];      // sigmoid spatial gate
__device__ float    g_encsum[4 * 128];
__device__ unsigned g_encmax[4 * 128];
__device__ float    g_decsum[4 * 256];
__device__ unsigned g_decmax[4 * 256];
__device__ __align__(16) float g_ch[4 * 128];       // sigmoid channel gate

// monotone float<->uint map for atomicMax/REDUX-max on floats
__device__ __forceinline__ unsigned f2o(float f) {
    unsigned u = __float_as_uint(f);
    return (u & 0x80000000u) ? ~u : (u | 0x80000000u);
}
__device__ __forceinline__ float o2f(unsigned u) {
    return (u & 0x80000000u) ? __uint_as_float(u & 0x7fffffffu) : __uint_as_float(~u);
}

// ================= init (atomic targets) =================
__global__ void k_init() {
    int t = blockIdx.x * blockDim.x + threadIdx.x;
    if (t < 512)  { g_encsum[t] = 0.f; g_encmax[t] = 0u; }
    if (t < 1024) { g_decsum[t] = 0.f; g_decmax[t] = 0x80000000u; }  // f2o(0); relu => v>=0
}

// ================= fused encoder: planes + channel stats =================
// grid (128, 4) x 128 threads: block = 2 rows; thread = (row, float4-col)
__global__ void __launch_bounds__(128) k_enc(const float* __restrict__ xe,
                                             const float* __restrict__ sw1e,
                                             const float* __restrict__ sb1e) {
    __shared__ float    sw[128];
    __shared__ float    psum[4][128];
    __shared__ unsigned pmax[4][128];
    const int t = threadIdx.x;
    if (t < 128) sw[t] = sw1e[t];
    __syncthreads();
    const int y = blockIdx.x * 2 + (t >> 6), c4 = t & 63, b = blockIdx.y;
    const int warp = t >> 5, lane = t & 31;
    const float4* base = (const float4*)(xe + (size_t)b * 128 * HW + y * 256) + c4;

    float4 mx = make_float4(-3.4e38f, -3.4e38f, -3.4e38f, -3.4e38f);
    float4 sm = make_float4(0.f, 0.f, 0.f, 0.f);
    float4 dt = make_float4(0.f, 0.f, 0.f, 0.f);
    float    racc[4] = {0.f, 0.f, 0.f, 0.f};
    unsigned rmx[4]  = {0u, 0u, 0u, 0u};

#pragma unroll
    for (int q = 0; q < 4; q++) {
#pragma unroll 4
        for (int cc = 0; cc < 32; cc++) {
            const int c = q * 32 + cc;
            float4 v = base[(size_t)c * (HW / 4)];
            float wc = sw[c];
            mx.x = fmaxf(mx.x, v.x); sm.x += v.x; dt.x = fmaf(wc, v.x, dt.x);
            mx.y = fmaxf(mx.y, v.y); sm.y += v.y; dt.y = fmaf(wc, v.y, dt.y);
            mx.z = fmaxf(mx.z, v.z); sm.z += v.z; dt.z = fmaf(wc, v.z, dt.z);
            mx.w = fmaxf(mx.w, v.w); sm.w += v.w; dt.w = fmaf(wc, v.w, dt.w);
            float cs = (v.x + v.y) + (v.z + v.w);
            float cm = fmaxf(fmaxf(v.x, v.y), fmaxf(v.z, v.w));
#pragma unroll
            for (int o = 16; o; o >>= 1)
                cs += __shfl_xor_sync(0xffffffffu, cs, o);
            unsigned rm = __reduce_max_sync(0xffffffffu, f2o(cm));
            if (lane == cc) { racc[q] += cs; rmx[q] = max(rmx[q], rm); }
        }
    }
#pragma unroll
    for (int q = 0; q < 4; q++) {
        psum[warp][q * 32 + lane] = racc[q];
        pmax[warp][q * 32 + lane] = rmx[q];
    }
    __syncthreads();
    if (t < 128) {
        float s = (psum[0][t] + psum[1][t]) + (psum[2][t] + psum[3][t]);
        unsigned m = max(max(pmax[0][t], pmax[1][t]), max(pmax[2][t], pmax[3][t]));
        atomicAdd(&g_encsum[b * 128 + t], s);
        atomicMax(&g_encmax[b * 128 + t], m);
    }
    const float b1 = sb1e[0];
    sm.x *= (1.f / 128.f); sm.y *= (1.f / 128.f); sm.z *= (1.f / 128.f); sm.w *= (1.f / 128.f);
    dt.x += b1; dt.y += b1; dt.z += b1; dt.w += b1;
    const size_t p4 = (size_t)(y * 256) / 4 + c4;
    float4* eb = (float4*)(g_sage + (size_t)b * 3 * HW);
    eb[p4]              = mx;
    eb[HW / 4 + p4]     = sm;
    eb[2 * HW / 4 + p4] = dt;
}

// ================= fused decoder: partial planes + channel stats =================
// grid (64, 2, 4): x = row-group (4 rows), y = channel half, z = b. 256 threads = columns.
// Writes PARTIAL (mx, raw sum, raw dot) planes per (half,b); k_conv combines.
// Per-channel stats: butterfly sum + REDUX max, banked (lane==c&31) into compile-time
// slots, one atomic pair per (block, channel) at the end.
__global__ void __launch_bounds__(256) k_dec_pix(const float* __restrict__ xd,
                                                 const float* __restrict__ sw1d) {
    __shared__ float    sw[128];
    __shared__ float    buf[2][8 * 512];   // [buf][q*512 + srcrow*128 + col]
    __shared__ float    psum[8][128];
    __shared__ unsigned pmaxs[8][128];
    const int t = threadIdx.x, half = blockIdx.y, b = blockIdx.z;
    const int warp = t >> 5, lane = t & 31;
    const int y0 = blockIdx.x * 4;
    if (t < 128) sw[t] = sw1d[half * 128 + t];

    const int rbase = (y0 * 127) / 255;
    int lo[4]; float wy[4];
#pragma unroll
    for (int k = 0; k < 4; k++) {
        const int y = y0 + k;
        const int i0 = (y * 127) / 255;          // exact floor
        lo[k] = i0 - rbase;                      // 0..2, uniform per block
        wy[k] = (float)y * RATIO - (float)i0;
    }
    float px = (float)t * RATIO;
    int j0 = min((int)floorf(px), 127), j1 = min(j0 + 1, 127);
    float wx = px - (float)j0;

    const int gA = min(rbase + (t >> 7), 127) * 128 + (t & 127);
    const int gB = min(rbase + 2 + (t >> 7), 127) * 128 + (t & 127);
    const float* pcb = xd + ((size_t)b * 256 + half * 128) * 16384;

#pragma unroll
    for (int q = 0; q < 8; q++) {
        buf[0][q * 512 + t]       = pcb[(size_t)q * 16384 + gA];
        buf[0][q * 512 + 256 + t] = pcb[(size_t)q * 16384 + gB];
    }
    __syncthreads();

    float mx[4] = {0, 0, 0, 0}, sm[4] = {0, 0, 0, 0}, dt[4] = {0, 0, 0, 0};
    float    racc[4] = {0.f, 0.f, 0.f, 0.f};
    unsigned rmx[4]  = {0x80000000u, 0x80000000u, 0x80000000u, 0x80000000u};

#pragma unroll
    for (int s = 0; s < 4; s++) {            // 32-channel slot (compile-time)
        for (int gi = 0; gi < 4; gi++) {     // 8-channel group within slot
            const int g = s * 4 + gi;
            const int cur = g & 1;
            float rr[16];
            const bool pf = (g < 15);
            if (pf) {
                const float* pn = pcb + (size_t)(g + 1) * 8 * 16384;
#pragma unroll
                for (int q = 0; q < 8; q++) {
                    rr[q * 2]     = pn[(size_t)q * 16384 + gA];
                    rr[q * 2 + 1] = pn[(size_t)q * 16384 + gB];
                }
            }
#pragma unroll
            for (int q = 0; q < 8; q++) {
                const int c = g * 8 + q;
                const float* S = &buf[cur][q * 512];
                float h0, h1, h2, h3;
                { float a = S[j0],       bb = S[j1];       h0 = fmaf(wx, bb - a, a); }
                { float a = S[128 + j0], bb = S[128 + j1]; h1 = fmaf(wx, bb - a, a); }
                { float a = S[256 + j0], bb = S[256 + j1]; h2 = fmaf(wx, bb - a, a); }
                { float a = S[384 + j0], bb = S[384 + j1]; h3 = fmaf(wx, bb - a, a); }
                const float wc = sw[c];
                float cs = 0.f, cm = 0.f;
#pragma unroll
                for (int k = 0; k < 4; k++) {
                    float hl = (lo[k] == 0) ? h0 : ((lo[k] == 1) ? h1 : h2);
                    float hh = (lo[k] == 0) ? h1 : ((lo[k] == 1) ? h2 : h3);
                    float v = fmaf(wy[k], hh - hl, hl);
                    v = fmaxf(v, 0.f);
                    mx[k] = fmaxf(mx[k], v);
                    sm[k] += v;
                    dt[k] = fmaf(wc, v, dt[k]);
                    cs += v;
                    cm = fmaxf(cm, v);
                }
#pragma unroll
                for (int o = 16; o; o >>= 1)
                    cs += __shfl_xor_sync(0xffffffffu, cs, o);
                unsigned rm = __reduce_max_sync(0xffffffffu, f2o(cm));
                if (lane == (c & 31)) { racc[s] += cs; rmx[s] = max(rmx[s], rm); }
            }
            if (pf) {
#pragma unroll
                for (int q = 0; q < 8; q++) {
                    buf[cur ^ 1][q * 512 + t]       = rr[q * 2];
                    buf[cur ^ 1][q * 512 + 256 + t] = rr[q * 2 + 1];
                }
            }
            __syncthreads();
        }
    }
    // bank stats: cross-warp combine, one atomic pair per (block, channel)
#pragma unroll
    for (int s = 0; s < 4; s++) {
        psum[warp][s * 32 + lane]  = racc[s];
        pmaxs[warp][s * 32 + lane] = rmx[s];
    }
    __syncthreads();
    if (t < 128) {
        float    ssum = 0.f;
        unsigned smx  = 0x80000000u;
#pragma unroll
        for (int w = 0; w < 8; w++) {
            ssum += psum[w][t];
            smx = max(smx, pmaxs[w][t]);
        }
        atomicAdd(&g_decsum[b * 256 + half * 128 + t], ssum);
        atomicMax(&g_decmax[b * 256 + half * 128 + t], smx);
    }
    const size_t db = (size_t)(half * 4 + b) * 3 * HW;
#pragma unroll
    for (int k = 0; k < 4; k++) {
        const int p = (y0 + k) * 256 + t;
        g_sagd[db + p]          = mx[k];
        g_sagd[db + HW + p]     = sm[k];
        g_sagd[db + 2 * HW + p] = dt[k];
    }
}

// ================= channel MLP (parallel) =================
__global__ void __launch_bounds__(256) k_mlp(
        const float* __restrict__ cwea, const float* __restrict__ cbea,
        const float* __restrict__ cwem, const float* __restrict__ cbem,
        const float* __restrict__ cwda, const float* __restrict__ cbda,
        const float* __restrict__ cwdm, const float* __restrict__ cbdm,
        const float* __restrict__ cwf,  const float* __restrict__ cbf) {
    __shared__ float part[256];
    __shared__ float tsm[16];
    const int b = blockIdx.x, t = threadIdx.x;
    const int n = t >> 4, ck = t & 15;
    float acc = 0.f;
#pragma unroll
    for (int i = 0; i < 8; i++) {
        int c = ck * 8 + i;
        acc += g_encsum[b * 128 + c] * (1.f / 65536.f) * cwea[n * 128 + c]
             + o2f(g_encmax[b * 128 + c]) * cwem[n * 128 + c];
    }
#pragma unroll
    for (int i = 0; i < 16; i++) {
        int c = ck * 16 + i;
        acc += g_decsum[b * 256 + c] * (1.f / 65536.f) * cwda[n * 256 + c]
             + o2f(g_decmax[b * 256 + c]) * cwdm[n * 256 + c];
    }
    if (ck == 0) acc += cbea[n] + cbem[n] + cbda[n] + cbdm[n];
    part[t] = acc;
    __syncthreads();
    for (int o = 8; o > 0; o >>= 1) {
        if (ck < o) part[t] += part[t + o];
        __syncthreads();
    }
    if (ck == 0) tsm[n] = part[t];
    __syncthreads();
    if (t < 128) {
        float a = cbf[t];
#pragma unroll
        for (int q = 0; q < 16; q++) a = fmaf(tsm[q], cwf[t * 16 + q], a);
        g_ch[b * 128 + t] = 1.f / (1.f + __expf(-a));
    }
}

// ================= fused 7x7 conv (6 planes, combines dec halves) + sigmoid =================
// grid (16, 16, 4): 16x16 output tile, 256 threads, 1 output/thread
__global__ void __launch_bounds__(256) k_conv(const float* __restrict__ sw2e,
                                              const float* __restrict__ sw2d,
                                              const float* __restrict__ sb2e,
                                              const float* __restrict__ sb2d,
                                              const float* __restrict__ sb1d) {
    __shared__ float pl[6][22 * 22];
    __shared__ float wsm[294];
    __shared__ float bv;
    const int tid = threadIdx.x;
    const int X0 = blockIdx.x * 16, Y0 = blockIdx.y * 16, b = blockIdx.z;
    for (int i = tid; i < 294; i += 256)
        wsm[i] = (i < 147) ? sw2e[i] : sw2d[i - 147];
    if (tid == 0) bv = sb2e[0] + sb2d[0];
    const float sb1 = __ldg(sb1d);
    const size_t eb = (size_t)b * 3 * HW;
    const size_t d0 = (size_t)b * 3 * HW;        // half 0
    const size_t d1 = (size_t)(4 + b) * 3 * HW;  // half 1
    for (int idx = tid; idx < 22 * 22; idx += 256) {
        int ry = idx / 22, rx = idx - ry * 22;
        int gy = Y0 + ry - 3, gx = X0 + rx - 3;
        float v0 = 0, v1 = 0, v2 = 0, v3 = 0, v4 = 0, v5 = 0;
        if (gy >= 0 && gy < 256 && gx >= 0 && gx < 256) {
            int p = gy * 256 + gx;
            v0 = g_sage[eb + p];
            v1 = g_sage[eb + HW + p];
            v2 = g_sage[eb + 2 * HW + p];
            v3 = fmaxf(g_sagd[d0 + p], g_sagd[d1 + p]);
            v4 = (g_sagd[d0 + HW + p] + g_sagd[d1 + HW + p]) * (1.f / 256.f);
            v5 = g_sagd[d0 + 2 * HW + p] + g_sagd[d1 + 2 * HW + p] + sb1;
        }
        pl[0][idx] = v0; pl[1][idx] = v1; pl[2][idx] = v2;
        pl[3][idx] = v3; pl[4][idx] = v4; pl[5][idx] = v5;
    }
    __syncthreads();
    const int tx = tid & 15, ty = tid >> 4;
    float acc = bv;
    for (int pp = 0; pp < 6; pp++)
#pragma unroll
        for (int ky = 0; ky < 7; ky++)
#pragma unroll
            for (int kx = 0; kx < 7; kx++)
                acc = fmaf(pl[pp][(ty + ky) * 22 + tx + kx], wsm[pp * 49 + ky * 7 + kx], acc);
    g_spat[(size_t)b * HW + (Y0 + ty) * 256 + X0 + tx] = 1.f / (1.f + __expf(-acc));
}

// ================= final multiply =================
__global__ void __launch_bounds__(256) k_final(const float* __restrict__ xe,
                                               float* __restrict__ out) {
    const int bc = blockIdx.y;
    const int b  = bc >> 7;
    const int i  = blockIdx.x * 256 + threadIdx.x;
    const float s = g_ch[bc];
    float4 xv = reinterpret_cast<const float4*>(xe)[(size_t)bc * 16384 + i];
    float4 sp = reinterpret_cast<const float4*>(g_spat)[(size_t)b * 16384 + i];
    float4 o;
    o.x = xv.x * sp.x * s;
    o.y = xv.y * sp.y * s;
    o.z = xv.z * sp.z * s;
    o.w = xv.w * sp.w * s;
    reinterpret_cast<float4*>(out)[(size_t)bc * 16384 + i] = o;
}

// ================= launch =================
extern "C" void kernel_launch(void* const* d_in, const int* in_sizes, int n_in,
                              void* d_out, int out_size) {
    const float* xe   = (const float*)d_in[0];
    const float* xd   = (const float*)d_in[1];
    const float* cwea = (const float*)d_in[2];
    const float* cbea = (const float*)d_in[3];
    const float* cwem = (const float*)d_in[4];
    const float* cbem = (const float*)d_in[5];
    const float* cwda = (const float*)d_in[6];
    const float* cbda = (const float*)d_in[7];
    const float* cwdm = (const float*)d_in[8];
    const float* cbdm = (const float*)d_in[9];
    const float* cwf  = (const float*)d_in[10];
    const float* cbf  = (const float*)d_in[11];
    const float* sw1e = (const float*)d_in[12];
    const float* sb1e = (const float*)d_in[13];
    const float* sw2e = (const float*)d_in[14];
    const float* sb2e = (const float*)d_in[15];
    const float* sw1d = (const float*)d_in[16];
    const float* sb1d = (const float*)d_in[17];
    const float* sw2d = (const float*)d_in[18];
    const float* sb2d = (const float*)d_in[19];
    float* out = (float*)d_out;

    k_init<<<1, 1024>>>();
    k_enc<<<dim3(128, 4), 128>>>(xe, sw1e, sb1e);
    k_dec_pix<<<dim3(64, 2, 4), 256>>>(xd, sw1d);
    k_mlp<<<4, 256>>>(cwea, cbea, cwem, cbem, cwda, cbda, cwdm, cbdm, cwf, cbf);
    k_conv<<<dim3(16, 16, 4), 256>>>(sw2e, sw2d, sb2e, sb2d, sb1d);
    k_final<<<dim3(64, 512), 256>>>(xe, out);
}